// round 10
// baseline (speedup 1.0000x reference)
#include <cuda_runtime.h>
#include <cstdint>

// Causal MHA, B=2, L=2048, H=16, E=64, fp32; reference scales scores by sqrt(E)=8.
// R9: R8 body (bf16 m16n8k16, 3-term QK / 3-term PV splits, 3 CTAs/SM,
// deferred l-reduction) with hi/lo INTERLEAVED smem buffers:
//   KHL[n][2*kpair] = (hi,lo), VHL[e][2*npair] = (hi,lo), row stride 72 uint32.
// One LDS.64 fetches both hi and lo B-halves -> 128 instead of 256 LDS per tile.

#define NT 128
#define BM 64
#define BN 64
#define ED 64
#define ST2 72   // uint32 row stride for KHL/VHL (72 % 32 == 8 -> conflict-free)
#define RVST 68  // float row stride for raw V tile

static constexpr int B_ = 2, L_ = 2048, H_ = 16;
static constexpr int RS = H_ * ED;                    // 1024 floats per seq row
static constexpr int SMEM_UINTS = 2 * BN * ST2 + BN * RVST;
static constexpr int SMEM_BYTES = SMEM_UINTS * 4;     // 54272 B

__device__ __forceinline__ uint32_t pack_bf16x2(float lo, float hi) {
    uint32_t d;   // PTX: first source -> upper half
    asm("cvt.rn.bf16x2.f32 %0, %1, %2;" : "=r"(d) : "f"(hi), "f"(lo));
    return d;
}
__device__ __forceinline__ float bf_lo(uint32_t u) { return __uint_as_float(u << 16); }
__device__ __forceinline__ float bf_hi(uint32_t u) { return __uint_as_float(u & 0xffff0000u); }

__device__ __forceinline__ float ex2(float x) {
    float y;
    asm("ex2.approx.f32 %0, %1;" : "=f"(y) : "f"(x));
    return y;
}

__device__ __forceinline__ void mma_bf16(float c[4],
                                         uint32_t a0, uint32_t a1, uint32_t a2, uint32_t a3,
                                         uint32_t b0, uint32_t b1) {
    asm volatile(
        "mma.sync.aligned.m16n8k16.row.col.f32.bf16.bf16.f32 "
        "{%0,%1,%2,%3}, {%4,%5,%6,%7}, {%8,%9}, {%0,%1,%2,%3};"
        : "+f"(c[0]), "+f"(c[1]), "+f"(c[2]), "+f"(c[3])
        : "r"(a0), "r"(a1), "r"(a2), "r"(a3), "r"(b0), "r"(b1));
}

__global__ __launch_bounds__(NT, 3) void attn_kernel(
    const float* __restrict__ Q, const float* __restrict__ K,
    const float* __restrict__ V, float* __restrict__ O)
{
    extern __shared__ uint32_t smu[];
    uint32_t* KHL = smu;                  // [64][ST2]: n rows, (hi,lo) k-pairs
    uint32_t* VHL = KHL + BN * ST2;       // [64][ST2]: e rows, (hi,lo) n-pairs
    float*    Vr  = reinterpret_cast<float*>(VHL + BN * ST2);  // [64][RVST] raw V

    const int tid  = threadIdx.x;
    const int lane = tid & 31;
    const int w    = tid >> 5;            // 0..3
    const int r    = lane >> 2;           // 0..7
    const int c    = lane & 3;            // 0..3
    const int qt = (int)gridDim.x - 1 - (int)blockIdx.x;   // heavy tiles first
    const int h  = blockIdx.y, b = blockIdx.z;
    const int q0 = qt * BM;
    const int m_lo = q0 + w * 16 + r;
    const size_t base = ((size_t)b * L_ * H_ + h) * ED;
    const float* Qp = Q + base;
    const float* Kp = K + base;
    const float* Vp = V + base;
    float*       Op = O + base;

    // ---- Q A-fragments: scale 8*log2(e), bf16 hi/lo split, resident ----
    const float QS = 8.f * 1.4426950408889634f;
    uint32_t qh[4][4], ql[4][4];
    #pragma unroll
    for (int kk = 0; kk < 4; ++kk) {
        const float* p = Qp + (size_t)m_lo * RS + kk * 16 + 2 * c;
        float2 x0 = *reinterpret_cast<const float2*>(p);
        float2 x1 = *reinterpret_cast<const float2*>(p + 8 * RS);
        float2 x2 = *reinterpret_cast<const float2*>(p + 8);
        float2 x3 = *reinterpret_cast<const float2*>(p + 8 * RS + 8);
        float f[4][2] = { {QS*x0.x, QS*x0.y}, {QS*x1.x, QS*x1.y},
                          {QS*x2.x, QS*x2.y}, {QS*x3.x, QS*x3.y} };
        #pragma unroll
        for (int i = 0; i < 4; ++i) {
            uint32_t hh = pack_bf16x2(f[i][0], f[i][1]);
            qh[kk][i] = hh;
            ql[kk][i] = pack_bf16x2(f[i][0] - bf_lo(hh), f[i][1] - bf_hi(hh));
        }
    }

    float acc[8][4];
    #pragma unroll
    for (int j = 0; j < 8; ++j)
        #pragma unroll
        for (int i = 0; i < 4; ++i) acc[j][i] = 0.f;

    float mr0 = -1e30f, mr1 = -1e30f;
    float l0 = 0.f, l1 = 0.f;             // per-lane partials; reduced in epilogue

    const int cp = lane & 3;
    const int rp = lane >> 2;

    const int nTiles = qt + 1;
    for (int kt = 0; kt < nTiles; ++kt) {
        const int k0 = kt * BN;
        __syncthreads();

        // ---- pass A: K convert-at-store (interleaved hi/lo); V raw to smem ----
        #pragma unroll
        for (int t = 0; t < 8; ++t) {
            int idx = tid + t * NT;
            int rr = idx >> 4;
            int cc = (idx & 15) * 4;
            float4 kf = *reinterpret_cast<const float4*>(Kp + (size_t)(k0 + rr) * RS + cc);
            uint32_t h01 = pack_bf16x2(kf.x, kf.y);
            uint32_t h23 = pack_bf16x2(kf.z, kf.w);
            uint32_t l01 = pack_bf16x2(kf.x - bf_lo(h01), kf.y - bf_hi(h01));
            uint32_t l23 = pack_bf16x2(kf.z - bf_lo(h23), kf.w - bf_hi(h23));
            // k-pairs cc/2, cc/2+1 -> uint32 offset 2*(cc/2) = cc (16B aligned)
            *reinterpret_cast<uint4*>(&KHL[rr * ST2 + cc]) =
                make_uint4(h01, l01, h23, l23);
            float4 vf = *reinterpret_cast<const float4*>(Vp + (size_t)(k0 + rr) * RS + cc);
            *reinterpret_cast<float4*>(&Vr[rr * RVST + cc]) = vf;
        }
        __syncthreads();

        // ---- pass B: transpose/pack V -> VHL [e][(hi,lo) n-pair] ----
        #pragma unroll
        for (int t = 0; t < 16; ++t) {
            int nb = t & 7;
            int eb = w + ((t >> 3) << 2);
            int np = nb * 4 + cp;
            int e  = eb * 8 + rp;
            float v0 = Vr[(2 * np)     * RVST + e];
            float v1 = Vr[(2 * np + 1) * RVST + e];
            uint32_t hh = pack_bf16x2(v0, v1);
            uint32_t ll = pack_bf16x2(v0 - bf_lo(hh), v1 - bf_hi(hh));
            *reinterpret_cast<uint2*>(&VHL[e * ST2 + 2 * np]) = make_uint2(hh, ll);
        }
        __syncthreads();

        // ---- S = Q K^T (log2 domain), 3-term bf16; LDS.64 fetches hi+lo ----
        float s[8][4];
        #pragma unroll
        for (int j = 0; j < 8; ++j)
            #pragma unroll
            for (int i = 0; i < 4; ++i) s[j][i] = 0.f;

        #pragma unroll
        for (int kk = 0; kk < 4; ++kk) {
            #pragma unroll
            for (int j = 0; j < 8; ++j) {
                const int ko = (j * 8 + r) * ST2 + (kk * 8 + c) * 2;
                uint2 kb0 = *reinterpret_cast<const uint2*>(&KHL[ko]);      // (bh0,bl0)
                uint2 kb1 = *reinterpret_cast<const uint2*>(&KHL[ko + 8]);  // (bh1,bl1)
                mma_bf16(s[j], qh[kk][0], qh[kk][1], qh[kk][2], qh[kk][3], kb0.x, kb1.x);
                mma_bf16(s[j], ql[kk][0], ql[kk][1], ql[kk][2], ql[kk][3], kb0.x, kb1.x);
                mma_bf16(s[j], qh[kk][0], qh[kk][1], qh[kk][2], qh[kk][3], kb0.y, kb1.y);
            }
        }

        // ---- causal mask (diagonal tile only) ----
        if (kt == qt) {
            #pragma unroll
            for (int j = 0; j < 8; ++j) {
                int n = k0 + j * 8 + 2 * c;
                if (n     > m_lo)     s[j][0] = -1e30f;
                if (n + 1 > m_lo)     s[j][1] = -1e30f;
                if (n     > m_lo + 8) s[j][2] = -1e30f;
                if (n + 1 > m_lo + 8) s[j][3] = -1e30f;
            }
        }

        // ---- online softmax: only MAX reduced; l stays per-lane ----
        float mx0 = -1e30f, mx1 = -1e30f;
        #pragma unroll
        for (int j = 0; j < 8; ++j) {
            mx0 = fmaxf(mx0, fmaxf(s[j][0], s[j][1]));
            mx1 = fmaxf(mx1, fmaxf(s[j][2], s[j][3]));
        }
        mx0 = fmaxf(mx0, __shfl_xor_sync(0xffffffffu, mx0, 1));
        mx0 = fmaxf(mx0, __shfl_xor_sync(0xffffffffu, mx0, 2));
        mx1 = fmaxf(mx1, __shfl_xor_sync(0xffffffffu, mx1, 1));
        mx1 = fmaxf(mx1, __shfl_xor_sync(0xffffffffu, mx1, 2));

        float mn0 = fmaxf(mr0, mx0), mn1 = fmaxf(mr1, mx1);
        float al0 = ex2(mr0 - mn0), al1 = ex2(mr1 - mn1);
        float sum0 = 0.f, sum1 = 0.f;
        #pragma unroll
        for (int j = 0; j < 8; ++j) {
            s[j][0] = ex2(s[j][0] - mn0);
            s[j][1] = ex2(s[j][1] - mn0);
            s[j][2] = ex2(s[j][2] - mn1);
            s[j][3] = ex2(s[j][3] - mn1);
            sum0 += s[j][0] + s[j][1];
            sum1 += s[j][2] + s[j][3];
        }
        l0 = l0 * al0 + sum0;
        l1 = l1 * al1 + sum1;
        mr0 = mn0; mr1 = mn1;

        #pragma unroll
        for (int j = 0; j < 8; ++j) {
            acc[j][0] *= al0; acc[j][1] *= al0;
            acc[j][2] *= al1; acc[j][3] *= al1;
        }

        // ---- O += P V : C-frag == A-frag, 3-term bf16; LDS.64 hi+lo ----
        #pragma unroll
        for (int kk = 0; kk < 4; ++kk) {
            float s00 = s[2*kk][0],   s01 = s[2*kk][1];
            float s10 = s[2*kk][2],   s11 = s[2*kk][3];
            float s20 = s[2*kk+1][0], s21 = s[2*kk+1][1];
            float s30 = s[2*kk+1][2], s31 = s[2*kk+1][3];
            uint32_t ph0 = pack_bf16x2(s00, s01);
            uint32_t ph1 = pack_bf16x2(s10, s11);
            uint32_t ph2 = pack_bf16x2(s20, s21);
            uint32_t ph3 = pack_bf16x2(s30, s31);
            uint32_t pl0 = pack_bf16x2(s00 - bf_lo(ph0), s01 - bf_hi(ph0));
            uint32_t pl1 = pack_bf16x2(s10 - bf_lo(ph1), s11 - bf_hi(ph1));
            uint32_t pl2 = pack_bf16x2(s20 - bf_lo(ph2), s21 - bf_hi(ph2));
            uint32_t pl3 = pack_bf16x2(s30 - bf_lo(ph3), s31 - bf_hi(ph3));
            #pragma unroll
            for (int jj = 0; jj < 8; ++jj) {
                const int vo = (jj * 8 + r) * ST2 + (kk * 8 + c) * 2;
                uint2 vb0 = *reinterpret_cast<const uint2*>(&VHL[vo]);      // (bh0,bl0)
                uint2 vb1 = *reinterpret_cast<const uint2*>(&VHL[vo + 8]);  // (bh1,bl1)
                mma_bf16(acc[jj], ph0, ph1, ph2, ph3, vb0.x, vb1.x);
                mma_bf16(acc[jj], pl0, pl1, pl2, pl3, vb0.x, vb1.x);
                mma_bf16(acc[jj], ph0, ph1, ph2, ph3, vb0.y, vb1.y);
            }
        }
    }

    // ---- epilogue: reduce l across the quad, normalize, store ----
    l0 += __shfl_xor_sync(0xffffffffu, l0, 1);
    l0 += __shfl_xor_sync(0xffffffffu, l0, 2);
    l1 += __shfl_xor_sync(0xffffffffu, l1, 1);
    l1 += __shfl_xor_sync(0xffffffffu, l1, 2);
    const float inv0 = 1.f / l0, inv1 = 1.f / l1;
    #pragma unroll
    for (int jj = 0; jj < 8; ++jj) {
        float2 o0 = { acc[jj][0] * inv0, acc[jj][1] * inv0 };
        float2 o1 = { acc[jj][2] * inv1, acc[jj][3] * inv1 };
        *reinterpret_cast<float2*>(Op + (size_t)m_lo * RS + jj * 8 + 2 * c) = o0;
        *reinterpret_cast<float2*>(Op + (size_t)(m_lo + 8) * RS + jj * 8 + 2 * c) = o1;
    }
}

extern "C" void kernel_launch(void* const* d_in, const int* in_sizes, int n_in,
                              void* d_out, int out_size)
{
    const float* Q = (const float*)d_in[0];
    const float* K = (const float*)d_in[1];
    const float* V = (const float*)d_in[2];
    // d_in[3] = attn_mask (causal triu(k=1)) — applied analytically in-kernel.
    float* O = (float*)d_out;

    cudaFuncSetAttribute(attn_kernel, cudaFuncAttributeMaxDynamicSharedMemorySize,
                         SMEM_BYTES);
    dim3 grid(L_ / BM, H_, B_);   // 32 x 16 x 2
    attn_kernel<<<grid, NT, SMEM_BYTES>>>(Q, K, V, O);
}

// round 11
// speedup vs baseline: 1.2586x; 1.2586x over previous
#include <cuda_runtime.h>
#include <cstdint>

// Causal MHA, B=2, L=2048, H=16, E=64, fp32; reference scales scores by sqrt(E)=8.
// R10: R8 math (bf16 m16n8k16, 3-term QK / 3-term PV hi-lo splits, 3 CTAs/SM,
// deferred l-reduction, log2-domain softmax) with ldmatrix-based fragments:
//   K and V both stored K-major as hi/lo bf16 arrays, row stride 72 b16 (144B).
//   QK B-frags: ldmatrix.m8n8.x4 (non-trans) on Kh/Kl.
//   PV B-frags: ldmatrix.m8n8.x4.trans on Vh/Vl  -> no V transpose pass, 2 barriers.

#define NT 128
#define BM 64
#define BN 64
#define ED 64
#define ST32 36                 // uint32 row stride = 72 b16 = 144 B (9 x 16B)

static constexpr int B_ = 2, L_ = 2048, H_ = 16;
static constexpr int RS = H_ * ED;                    // 1024 floats per seq row
static constexpr int ARR = BN * ST32;                 // 2304 uint32 per array
static constexpr int SMEM_UINTS = 4 * ARR;            // Kh, Kl, Vh, Vl
static constexpr int SMEM_BYTES = SMEM_UINTS * 4;     // 36864 B

__device__ __forceinline__ uint32_t pack_bf16x2(float lo, float hi) {
    uint32_t d;   // PTX: first source -> upper half
    asm("cvt.rn.bf16x2.f32 %0, %1, %2;" : "=r"(d) : "f"(hi), "f"(lo));
    return d;
}
__device__ __forceinline__ float bf_lo(uint32_t u) { return __uint_as_float(u << 16); }
__device__ __forceinline__ float bf_hi(uint32_t u) { return __uint_as_float(u & 0xffff0000u); }

__device__ __forceinline__ float ex2(float x) {
    float y;
    asm("ex2.approx.f32 %0, %1;" : "=f"(y) : "f"(x));
    return y;
}

__device__ __forceinline__ void ldsm4(uint32_t& d0, uint32_t& d1,
                                      uint32_t& d2, uint32_t& d3, uint32_t a) {
    asm volatile("ldmatrix.sync.aligned.m8n8.x4.shared.b16 {%0,%1,%2,%3}, [%4];"
                 : "=r"(d0), "=r"(d1), "=r"(d2), "=r"(d3) : "r"(a));
}
__device__ __forceinline__ void ldsm4t(uint32_t& d0, uint32_t& d1,
                                       uint32_t& d2, uint32_t& d3, uint32_t a) {
    asm volatile("ldmatrix.sync.aligned.m8n8.x4.trans.shared.b16 {%0,%1,%2,%3}, [%4];"
                 : "=r"(d0), "=r"(d1), "=r"(d2), "=r"(d3) : "r"(a));
}

__device__ __forceinline__ void mma_bf16(float c[4],
                                         uint32_t a0, uint32_t a1, uint32_t a2, uint32_t a3,
                                         uint32_t b0, uint32_t b1) {
    asm volatile(
        "mma.sync.aligned.m16n8k16.row.col.f32.bf16.bf16.f32 "
        "{%0,%1,%2,%3}, {%4,%5,%6,%7}, {%8,%9}, {%0,%1,%2,%3};"
        : "+f"(c[0]), "+f"(c[1]), "+f"(c[2]), "+f"(c[3])
        : "r"(a0), "r"(a1), "r"(a2), "r"(a3), "r"(b0), "r"(b1));
}

__global__ __launch_bounds__(NT, 3) void attn_kernel(
    const float* __restrict__ Q, const float* __restrict__ K,
    const float* __restrict__ V, float* __restrict__ O)
{
    extern __shared__ uint32_t smu[];
    uint32_t* Khm = smu;                  // [64 n][36 u32] k-pairs, hi
    uint32_t* Klm = Khm + ARR;            // lo
    uint32_t* Vhm = Klm + ARR;            // [64 n][36 u32] e-pairs, hi
    uint32_t* Vlm = Vhm + ARR;            // lo

    const uint32_t smb = (uint32_t)__cvta_generic_to_shared(smu);
    const uint32_t KhB = smb;
    const uint32_t KlB = smb + ARR * 4;
    const uint32_t VhB = smb + 2 * ARR * 4;
    const uint32_t VlB = smb + 3 * ARR * 4;

    const int tid  = threadIdx.x;
    const int lane = tid & 31;
    const int w    = tid >> 5;            // 0..3
    const int r    = lane >> 2;           // 0..7
    const int c    = lane & 3;            // 0..3
    const int rr8  = lane & 7;            // ldmatrix row within matrix
    const int msel = lane >> 3;           // ldmatrix matrix select 0..3
    const int qt = (int)gridDim.x - 1 - (int)blockIdx.x;   // heavy tiles first
    const int h  = blockIdx.y, b = blockIdx.z;
    const int q0 = qt * BM;
    const int m_lo = q0 + w * 16 + r;
    const size_t base = ((size_t)b * L_ * H_ + h) * ED;
    const float* Qp = Q + base;
    const float* Kp = K + base;
    const float* Vp = V + base;
    float*       Op = O + base;

    // ldmatrix per-lane byte offsets:
    // K x4 mats: (j,b0),(j,b1),(j+1,b0),(j+1,b1); rows = n, col byte = 32*kk(+16)
    const uint32_t laneK = (uint32_t)(((msel >> 1) * 8 + rr8) * 144 + (msel & 1) * 16);
    // V x4 mats: (jj,b0),(jj,b1),(jj+1,b0),(jj+1,b1); rows = n(16kk base), col = 16*jj
    const uint32_t laneV = (uint32_t)(((msel & 1) * 8 + rr8) * 144 + (msel >> 1) * 16);

    // ---- Q A-fragments: scale 8*log2(e), bf16 hi/lo split, resident ----
    const float QS = 8.f * 1.4426950408889634f;
    uint32_t qh[4][4], ql[4][4];
    #pragma unroll
    for (int kk = 0; kk < 4; ++kk) {
        const float* p = Qp + (size_t)m_lo * RS + kk * 16 + 2 * c;
        float2 x0 = *reinterpret_cast<const float2*>(p);
        float2 x1 = *reinterpret_cast<const float2*>(p + 8 * RS);
        float2 x2 = *reinterpret_cast<const float2*>(p + 8);
        float2 x3 = *reinterpret_cast<const float2*>(p + 8 * RS + 8);
        float f[4][2] = { {QS*x0.x, QS*x0.y}, {QS*x1.x, QS*x1.y},
                          {QS*x2.x, QS*x2.y}, {QS*x3.x, QS*x3.y} };
        #pragma unroll
        for (int i = 0; i < 4; ++i) {
            uint32_t hh = pack_bf16x2(f[i][0], f[i][1]);
            qh[kk][i] = hh;
            ql[kk][i] = pack_bf16x2(f[i][0] - bf_lo(hh), f[i][1] - bf_hi(hh));
        }
    }

    float acc[8][4];
    #pragma unroll
    for (int j = 0; j < 8; ++j)
        #pragma unroll
        for (int i = 0; i < 4; ++i) acc[j][i] = 0.f;

    float mr0 = -1e30f, mr1 = -1e30f;
    float l0 = 0.f, l1 = 0.f;             // per-lane partials; reduced in epilogue

    const int nTiles = qt + 1;
    for (int kt = 0; kt < nTiles; ++kt) {
        const int k0 = kt * BN;
        __syncthreads();                  // prev tile's reads done before overwrite

        // ---- staging: K and V convert-at-store, both K-major hi/lo ----
        #pragma unroll
        for (int t = 0; t < 8; ++t) {
            int idx = tid + t * NT;       // 1024 float4 slots
            int rw = idx >> 4;            // row n
            int cc = (idx & 15) * 4;      // col (k or e)
            float4 kf = *reinterpret_cast<const float4*>(Kp + (size_t)(k0 + rw) * RS + cc);
            uint32_t kh01 = pack_bf16x2(kf.x, kf.y);
            uint32_t kh23 = pack_bf16x2(kf.z, kf.w);
            uint32_t kl01 = pack_bf16x2(kf.x - bf_lo(kh01), kf.y - bf_hi(kh01));
            uint32_t kl23 = pack_bf16x2(kf.z - bf_lo(kh23), kf.w - bf_hi(kh23));
            *reinterpret_cast<uint2*>(&Khm[rw * ST32 + (cc >> 1)]) = make_uint2(kh01, kh23);
            *reinterpret_cast<uint2*>(&Klm[rw * ST32 + (cc >> 1)]) = make_uint2(kl01, kl23);
            float4 vf = *reinterpret_cast<const float4*>(Vp + (size_t)(k0 + rw) * RS + cc);
            uint32_t vh01 = pack_bf16x2(vf.x, vf.y);
            uint32_t vh23 = pack_bf16x2(vf.z, vf.w);
            uint32_t vl01 = pack_bf16x2(vf.x - bf_lo(vh01), vf.y - bf_hi(vh01));
            uint32_t vl23 = pack_bf16x2(vf.z - bf_lo(vh23), vf.w - bf_hi(vh23));
            *reinterpret_cast<uint2*>(&Vhm[rw * ST32 + (cc >> 1)]) = make_uint2(vh01, vh23);
            *reinterpret_cast<uint2*>(&Vlm[rw * ST32 + (cc >> 1)]) = make_uint2(vl01, vl23);
        }
        __syncthreads();

        // ---- S = Q K^T (log2 domain), 3-term bf16, ldmatrix B-frags ----
        float s[8][4];
        #pragma unroll
        for (int j = 0; j < 8; ++j)
            #pragma unroll
            for (int i = 0; i < 4; ++i) s[j][i] = 0.f;

        #pragma unroll
        for (int kk = 0; kk < 4; ++kk) {
            #pragma unroll
            for (int jp = 0; jp < 4; ++jp) {
                const uint32_t off = laneK + jp * 2304 + kk * 32;
                uint32_t kh0, kh1, kh2, kh3, kl0, kl1, kl2, kl3;
                ldsm4(kh0, kh1, kh2, kh3, KhB + off);
                ldsm4(kl0, kl1, kl2, kl3, KlB + off);
                mma_bf16(s[2*jp],   qh[kk][0], qh[kk][1], qh[kk][2], qh[kk][3], kh0, kh1);
                mma_bf16(s[2*jp],   ql[kk][0], ql[kk][1], ql[kk][2], ql[kk][3], kh0, kh1);
                mma_bf16(s[2*jp],   qh[kk][0], qh[kk][1], qh[kk][2], qh[kk][3], kl0, kl1);
                mma_bf16(s[2*jp+1], qh[kk][0], qh[kk][1], qh[kk][2], qh[kk][3], kh2, kh3);
                mma_bf16(s[2*jp+1], ql[kk][0], ql[kk][1], ql[kk][2], ql[kk][3], kh2, kh3);
                mma_bf16(s[2*jp+1], qh[kk][0], qh[kk][1], qh[kk][2], qh[kk][3], kl2, kl3);
            }
        }

        // ---- causal mask (diagonal tile only) ----
        if (kt == qt) {
            #pragma unroll
            for (int j = 0; j < 8; ++j) {
                int n = k0 + j * 8 + 2 * c;
                if (n     > m_lo)     s[j][0] = -1e30f;
                if (n + 1 > m_lo)     s[j][1] = -1e30f;
                if (n     > m_lo + 8) s[j][2] = -1e30f;
                if (n + 1 > m_lo + 8) s[j][3] = -1e30f;
            }
        }

        // ---- online softmax: only MAX reduced; l stays per-lane ----
        float mx0 = -1e30f, mx1 = -1e30f;
        #pragma unroll
        for (int j = 0; j < 8; ++j) {
            mx0 = fmaxf(mx0, fmaxf(s[j][0], s[j][1]));
            mx1 = fmaxf(mx1, fmaxf(s[j][2], s[j][3]));
        }
        mx0 = fmaxf(mx0, __shfl_xor_sync(0xffffffffu, mx0, 1));
        mx0 = fmaxf(mx0, __shfl_xor_sync(0xffffffffu, mx0, 2));
        mx1 = fmaxf(mx1, __shfl_xor_sync(0xffffffffu, mx1, 1));
        mx1 = fmaxf(mx1, __shfl_xor_sync(0xffffffffu, mx1, 2));

        float mn0 = fmaxf(mr0, mx0), mn1 = fmaxf(mr1, mx1);
        float al0 = ex2(mr0 - mn0), al1 = ex2(mr1 - mn1);
        float sum0 = 0.f, sum1 = 0.f;
        #pragma unroll
        for (int j = 0; j < 8; ++j) {
            s[j][0] = ex2(s[j][0] - mn0);
            s[j][1] = ex2(s[j][1] - mn0);
            s[j][2] = ex2(s[j][2] - mn1);
            s[j][3] = ex2(s[j][3] - mn1);
            sum0 += s[j][0] + s[j][1];
            sum1 += s[j][2] + s[j][3];
        }
        l0 = l0 * al0 + sum0;
        l1 = l1 * al1 + sum1;
        mr0 = mn0; mr1 = mn1;

        #pragma unroll
        for (int j = 0; j < 8; ++j) {
            acc[j][0] *= al0; acc[j][1] *= al0;
            acc[j][2] *= al1; acc[j][3] *= al1;
        }

        // ---- O += P V : C-frag == A-frag, 3-term bf16, ldmatrix.trans B ----
        #pragma unroll
        for (int kk = 0; kk < 4; ++kk) {
            float s00 = s[2*kk][0],   s01 = s[2*kk][1];
            float s10 = s[2*kk][2],   s11 = s[2*kk][3];
            float s20 = s[2*kk+1][0], s21 = s[2*kk+1][1];
            float s30 = s[2*kk+1][2], s31 = s[2*kk+1][3];
            uint32_t ph0 = pack_bf16x2(s00, s01);
            uint32_t ph1 = pack_bf16x2(s10, s11);
            uint32_t ph2 = pack_bf16x2(s20, s21);
            uint32_t ph3 = pack_bf16x2(s30, s31);
            uint32_t pl0 = pack_bf16x2(s00 - bf_lo(ph0), s01 - bf_hi(ph0));
            uint32_t pl1 = pack_bf16x2(s10 - bf_lo(ph1), s11 - bf_hi(ph1));
            uint32_t pl2 = pack_bf16x2(s20 - bf_lo(ph2), s21 - bf_hi(ph2));
            uint32_t pl3 = pack_bf16x2(s30 - bf_lo(ph3), s31 - bf_hi(ph3));
            #pragma unroll
            for (int jp = 0; jp < 4; ++jp) {
                const uint32_t off = laneV + kk * 2304 + jp * 32;
                uint32_t vh0, vh1, vh2, vh3, vl0, vl1, vl2, vl3;
                ldsm4t(vh0, vh1, vh2, vh3, VhB + off);
                ldsm4t(vl0, vl1, vl2, vl3, VlB + off);
                mma_bf16(acc[2*jp],   ph0, ph1, ph2, ph3, vh0, vh1);
                mma_bf16(acc[2*jp],   pl0, pl1, pl2, pl3, vh0, vh1);
                mma_bf16(acc[2*jp],   ph0, ph1, ph2, ph3, vl0, vl1);
                mma_bf16(acc[2*jp+1], ph0, ph1, ph2, ph3, vh2, vh3);
                mma_bf16(acc[2*jp+1], pl0, pl1, pl2, pl3, vh2, vh3);
                mma_bf16(acc[2*jp+1], ph0, ph1, ph2, ph3, vl2, vl3);
            }
        }
    }

    // ---- epilogue: reduce l across the quad, normalize, store ----
    l0 += __shfl_xor_sync(0xffffffffu, l0, 1);
    l0 += __shfl_xor_sync(0xffffffffu, l0, 2);
    l1 += __shfl_xor_sync(0xffffffffu, l1, 1);
    l1 += __shfl_xor_sync(0xffffffffu, l1, 2);
    const float inv0 = 1.f / l0, inv1 = 1.f / l1;
    #pragma unroll
    for (int jj = 0; jj < 8; ++jj) {
        float2 o0 = { acc[jj][0] * inv0, acc[jj][1] * inv0 };
        float2 o1 = { acc[jj][2] * inv1, acc[jj][3] * inv1 };
        *reinterpret_cast<float2*>(Op + (size_t)m_lo * RS + jj * 8 + 2 * c) = o0;
        *reinterpret_cast<float2*>(Op + (size_t)(m_lo + 8) * RS + jj * 8 + 2 * c) = o1;
    }
}

extern "C" void kernel_launch(void* const* d_in, const int* in_sizes, int n_in,
                              void* d_out, int out_size)
{
    const float* Q = (const float*)d_in[0];
    const float* K = (const float*)d_in[1];
    const float* V = (const float*)d_in[2];
    // d_in[3] = attn_mask (causal triu(k=1)) — applied analytically in-kernel.
    float* O = (float*)d_out;

    cudaFuncSetAttribute(attn_kernel, cudaFuncAttributeMaxDynamicSharedMemorySize,
                         SMEM_BYTES);
    dim3 grid(L_ / BM, H_, B_);   // 32 x 16 x 2
    attn_kernel<<<grid, NT, SMEM_BYTES>>>(Q, K, V, O);
}